// round 9
// baseline (speedup 1.0000x reference)
#include <cuda_runtime.h>
#include <cuda_fp16.h>
#include <cstdint>
#include <cstddef>

// ---------------------------------------------------------------------------
// Problem dims
// ---------------------------------------------------------------------------
#define BATCH 4096
#define HID   2048
#define CDIM  4096          // K (combined = hidden + input)
#define NDIM  8192          // 4*HID, W rows interleaved as 4*j + g (f,i,c,o)

// GEMM tiling (legacy mma.sync path -- base sm_103 target has no tcgen05)
#define BM 128
#define BN 256
#define BK 32
#define NKITERS (CDIM / BK)   // 128
#define STAGES 4

#define A_BYTES   (BM * BK * 2)        // 8192
#define B_BYTES   (BN * BK * 2)        // 16384
#define STG_BYTES (A_BYTES + B_BYTES)  // 24576
#define SMEM_TOTAL (STAGES * STG_BYTES) // 98304

// Epilogue gate buffer (reuses pipeline smem): 128 rows x 132 floats
#define SMG_STRIDE 132                 // 528 B/row: 16B aligned, bank-friendly

// fp16 GEMM operand scratch
__device__ __align__(1024) __half g_A[(size_t)BATCH * CDIM];  // [B, C]
__device__ __align__(1024) __half g_W[(size_t)NDIM * CDIM];   // interleaved [4H, C]

// ---------------------------------------------------------------------------
// PTX helpers (portable sm_80+ instructions only)
// ---------------------------------------------------------------------------
__device__ __forceinline__ uint32_t smem_u32(const void* p) {
    uint32_t a;
    asm("{ .reg .u64 t; cvta.to.shared.u64 t, %1; cvt.u32.u64 %0, t; }"
        : "=r"(a) : "l"(p));
    return a;
}
__device__ __forceinline__ void cp_async16(uint32_t dst, const void* src) {
    asm volatile("cp.async.cg.shared.global [%0], [%1], 16;"
                 :: "r"(dst), "l"(src) : "memory");
}
__device__ __forceinline__ void cp_commit() {
    asm volatile("cp.async.commit_group;" ::: "memory");
}
__device__ __forceinline__ void cp_wait2() {
    asm volatile("cp.async.wait_group 2;" ::: "memory");
}
__device__ __forceinline__ void cp_wait0() {
    asm volatile("cp.async.wait_group 0;" ::: "memory");
}
__device__ __forceinline__ void ldmatrix_x4(uint32_t* r, uint32_t addr) {
    asm volatile("ldmatrix.sync.aligned.m8n8.x4.shared.b16 {%0,%1,%2,%3}, [%4];"
                 : "=r"(r[0]), "=r"(r[1]), "=r"(r[2]), "=r"(r[3]) : "r"(addr));
}
__device__ __forceinline__ void mma16816(float* d, const uint32_t* a,
                                         uint32_t b0, uint32_t b1) {
    asm volatile(
        "mma.sync.aligned.m16n8k16.row.col.f32.f16.f16.f32 "
        "{%0,%1,%2,%3}, {%4,%5,%6,%7}, {%8,%9}, {%0,%1,%2,%3};"
        : "+f"(d[0]), "+f"(d[1]), "+f"(d[2]), "+f"(d[3])
        : "r"(a[0]), "r"(a[1]), "r"(a[2]), "r"(a[3]), "r"(b0), "r"(b1));
}

// XOR swizzle on 64-byte rows (4 x 16B chunks): chunk' = chunk ^ ((row>>1)&3)
// -> conflict-free ldmatrix phases (rows r, r+2, r+4, r+6 hit distinct chunks)
__device__ __forceinline__ uint32_t sw_off(int row, int kchunk) {
    return (uint32_t)(row * 64 + ((kchunk ^ ((row >> 1) & 3)) * 16));
}

// ---------------------------------------------------------------------------
// Convert kernels: fp32 -> fp16 operand scratch
// ---------------------------------------------------------------------------
__global__ void __launch_bounds__(256)
convert_A_kernel(const float* __restrict__ x_t, const float* __restrict__ h_prev) {
    int i = blockIdx.x * 256 + threadIdx.x;   // one 4-element chunk
    int row  = i >> 10;                       // CDIM/4 = 1024 chunks per row
    int col4 = (i & 1023) * 4;
    float4 v;
    if (col4 < HID)
        v = *(const float4*)(h_prev + (size_t)row * HID + col4);
    else
        v = *(const float4*)(x_t + (size_t)row * 2048 + (col4 - HID));
    __half2* dst = (__half2*)(g_A + (size_t)row * CDIM + col4);
    dst[0] = __floats2half2_rn(v.x, v.y);
    dst[1] = __floats2half2_rn(v.z, v.w);
}

__global__ void __launch_bounds__(256)
convert_W_kernel(const float* __restrict__ Wf, const float* __restrict__ Wi,
                 const float* __restrict__ Wc, const float* __restrict__ Wo) {
    int i = blockIdx.x * 256 + threadIdx.x;
    int row  = i >> 10;                       // 0..8191 (interleaved row 4j+g)
    int col4 = (i & 1023) * 4;
    int g = row & 3;
    int j = row >> 2;
    const float* src = (g == 0) ? Wf : (g == 1) ? Wi : (g == 2) ? Wc : Wo;
    float4 v = *(const float4*)(src + (size_t)j * CDIM + col4);
    __half2* dst = (__half2*)(g_W + (size_t)row * CDIM + col4);
    dst[0] = __floats2half2_rn(v.x, v.y);
    dst[1] = __floats2half2_rn(v.z, v.w);
}

// ---------------------------------------------------------------------------
// Fused GEMM (mma.sync HMMA) + LSTM epilogue
// 512 threads = 16 warps in a 4x4 grid; warp tile 32(m) x 64(n)
// ---------------------------------------------------------------------------
__global__ void __launch_bounds__(512, 1)
lstm_gemm_kernel(const float* __restrict__ c_prev,
                 const float* __restrict__ bf_, const float* __restrict__ bi_,
                 const float* __restrict__ bc_, const float* __restrict__ bo_,
                 float* __restrict__ out) {
    extern __shared__ char smem[];
    const uint32_t sbase = smem_u32(smem);

    const int tid  = threadIdx.x;
    const int lane = tid & 31;
    const int wid  = tid >> 5;
    const int wm   = wid & 3;   // warp row   (m tile = wm*32)
    const int wn   = wid >> 2;  // warp col   (n tile = wn*64)
    const int m0 = blockIdx.x * BM;
    const int n0 = blockIdx.y * BN;

    const __half* gA = g_A + (size_t)m0 * CDIM;
    const __half* gB = g_W + (size_t)n0 * CDIM;

    float acc[2][8][4];
    #pragma unroll
    for (int mi = 0; mi < 2; mi++)
        #pragma unroll
        for (int ni = 0; ni < 8; ni++)
            #pragma unroll
            for (int q = 0; q < 4; q++) acc[mi][ni][q] = 0.0f;

    auto load_stage = [&](int slot, int kiter) {
        const uint32_t sA = sbase + slot * STG_BYTES;
        const uint32_t sB = sA + A_BYTES;
        const int kk = kiter * BK;
        {   // A tile: 128 rows x 32 halves = 512 x 16B chunks (1 per thread)
            int r = tid >> 2, kc = tid & 3;
            cp_async16(sA + sw_off(r, kc), gA + (size_t)r * CDIM + kk + kc * 8);
        }
        #pragma unroll
        for (int i = 0; i < 2; i++) {  // B tile: 256 rows -> 1024 chunks
            int c = tid + i * 512;
            int r = c >> 2, kc = c & 3;
            cp_async16(sB + sw_off(r, kc), gB + (size_t)r * CDIM + kk + kc * 8);
        }
    };

    // Prologue: stages 0..2 in flight
    #pragma unroll
    for (int s = 0; s < STAGES - 1; s++) { load_stage(s, s); cp_commit(); }

    // ldmatrix lane address components
    const int a_row_l = lane & 15;        // A: rows mbase + (lane%16)
    const int a_ksel  = lane >> 4;        //    k-octet select
    const int b_row_l = (lane & 7) + ((lane & 16) >> 1);  // B: 2 n-octets
    const int b_ksel  = (lane >> 3) & 1;

    for (int k = 0; k < NKITERS; k++) {
        cp_wait2();          // stage k resident
        __syncthreads();     // all warps done with stage k-1's buffer; k visible
        int kt = k + STAGES - 1;
        if (kt < NKITERS) load_stage(kt & (STAGES - 1), kt);
        cp_commit();         // commit every iter (possibly empty) for wait math

        const uint32_t sA = sbase + (k & (STAGES - 1)) * STG_BYTES;
        const uint32_t sB = sA + A_BYTES;

        #pragma unroll
        for (int ks = 0; ks < 2; ks++) {      // two K=16 steps per BK=32
            uint32_t a[2][4];
            #pragma unroll
            for (int mi = 0; mi < 2; mi++) {
                int row = wm * 32 + mi * 16 + a_row_l;
                int kc  = ks * 2 + a_ksel;
                ldmatrix_x4(a[mi], sA + sw_off(row, kc));
            }
            #pragma unroll
            for (int np = 0; np < 4; np++) {  // each x4 yields 2 n-octets
                int nrow = wn * 64 + np * 16 + b_row_l;
                int kc   = ks * 2 + b_ksel;
                uint32_t b[4];
                ldmatrix_x4(b, sB + sw_off(nrow, kc));
                #pragma unroll
                for (int mi = 0; mi < 2; mi++) {
                    mma16816(acc[mi][np * 2 + 0], a[mi], b[0], b[1]);
                    mma16816(acc[mi][np * 2 + 1], a[mi], b[2], b[3]);
                }
            }
        }
    }
    cp_wait0();
    __syncthreads();

    // --- Fused epilogue: two 128-col passes through padded SMEM ---
    float* smG = (float*)smem;
    float* outH = out;
    float* outC = out + (size_t)BATCH * HID;

    #pragma unroll
    for (int p = 0; p < 2; p++) {
        if ((wn >> 1) == p) {            // warps owning cols [p*128, p*128+128)
            int colbase = (wn & 1) * 64;
            #pragma unroll
            for (int mi = 0; mi < 2; mi++)
                #pragma unroll
                for (int ni = 0; ni < 8; ni++) {
                    int r  = wm * 32 + mi * 16 + (lane >> 2);
                    int cc = colbase + ni * 8 + (lane & 3) * 2;
                    *(float2*)&smG[r * SMG_STRIDE + cc] =
                        make_float2(acc[mi][ni][0], acc[mi][ni][1]);
                    *(float2*)&smG[(r + 8) * SMG_STRIDE + cc] =
                        make_float2(acc[mi][ni][2], acc[mi][ni][3]);
                }
        }
        __syncthreads();

        const int j0 = (n0 >> 2) + p * 32;
        #pragma unroll
        for (int it = 0; it < 8; it++) {     // 4096 outputs / 512 threads
            int idx = tid + it * 512;
            int r = idx >> 5, jl = idx & 31;
            float4 g4 = *(const float4*)&smG[r * SMG_STRIDE + jl * 4];
            int j = j0 + jl;
            float gf = g4.x + __ldg(bf_ + j);
            float gi = g4.y + __ldg(bi_ + j);
            float gc = g4.z + __ldg(bc_ + j);
            float go = g4.w + __ldg(bo_ + j);
            float f  = 1.0f / (1.0f + __expf(-gf));
            float ii = 1.0f / (1.0f + __expf(-gi));
            float ct = tanhf(gc);
            float o  = 1.0f / (1.0f + __expf(-go));
            size_t gidx = (size_t)(m0 + r) * HID + j;
            float cn = f * c_prev[gidx] + ii * ct;
            outC[gidx] = cn;
            outH[gidx] = o * tanhf(cn);
        }
        __syncthreads();   // buffer reuse between passes
    }
}

// ---------------------------------------------------------------------------
// Launch
// ---------------------------------------------------------------------------
extern "C" void kernel_launch(void* const* d_in, const int* in_sizes, int n_in,
                              void* d_out, int out_size) {
    const float* x_t    = (const float*)d_in[0];
    const float* h_prev = (const float*)d_in[1];
    const float* c_prev = (const float*)d_in[2];
    const float* W_f = (const float*)d_in[3];
    const float* b_f = (const float*)d_in[4];
    const float* W_i = (const float*)d_in[5];
    const float* b_i = (const float*)d_in[6];
    const float* W_c = (const float*)d_in[7];
    const float* b_c = (const float*)d_in[8];
    const float* W_o = (const float*)d_in[9];
    const float* b_o = (const float*)d_in[10];
    float* out = (float*)d_out;

    cudaFuncSetAttribute(lstm_gemm_kernel,
                         cudaFuncAttributeMaxDynamicSharedMemorySize, SMEM_TOTAL);

    convert_A_kernel<<<(BATCH * CDIM / 4) / 256, 256>>>(x_t, h_prev);
    convert_W_kernel<<<(NDIM * CDIM / 4) / 256, 256>>>(W_f, W_i, W_c, W_o);

    dim3 grid(BATCH / BM, NDIM / BN);   // 32 x 32 = 1024 CTAs
    lstm_gemm_kernel<<<grid, 512, SMEM_TOTAL>>>(c_prev, b_f, b_i, b_c, b_o, out);
}

// round 10
// speedup vs baseline: 1.2064x; 1.2064x over previous
#include <cuda_runtime.h>
#include <cuda.h>
#include <cuda_fp16.h>
#include <cstdint>
#include <cstddef>

// ---------------------------------------------------------------------------
// Problem dims
// ---------------------------------------------------------------------------
#define BATCH 4096
#define HID   2048
#define CDIM  4096          // K (combined = hidden + input)
#define NDIM  8192          // 4*HID, W rows interleaved as 4*j + g (f,i,c,o)

// GEMM tiling (mma.sync HMMA path; TMA feeds SMEM)
#define BM 128
#define BN 256
#define BK 64               // 64 halves = 128 B per row (SW128 atom width)
#define NKITERS (CDIM / BK) // 64
#define STAGES 4

#define A_BYTES   (BM * BK * 2)        // 16384
#define B_BYTES   (BN * BK * 2)        // 32768
#define STG_BYTES (A_BYTES + B_BYTES)  // 49152

// SMEM (relative to 1024-aligned base): [0..32) 4 mbarriers, stages at +1024
#define OFF_STG    1024
#define SMEM_TOTAL (1024 + OFF_STG + STAGES * STG_BYTES)  // 198656 (alignment slack)

// Epilogue gate buffer (reuses stage region): 128 rows x 132 floats
#define SMG_STRIDE 132

// fp16 GEMM operand scratch
__device__ __align__(1024) __half g_A[(size_t)BATCH * CDIM];  // [B, C]
__device__ __align__(1024) __half g_W[(size_t)NDIM * CDIM];   // interleaved [4H, C]

// ---------------------------------------------------------------------------
// PTX helpers (base sm_90-level instructions only -- ptxas target is sm_103)
// ---------------------------------------------------------------------------
__device__ __forceinline__ uint32_t smem_u32(const void* p) {
    uint32_t a;
    asm("{ .reg .u64 t; cvta.to.shared.u64 t, %1; cvt.u32.u64 %0, t; }"
        : "=r"(a) : "l"(p));
    return a;
}
__device__ __forceinline__ void mbar_init(uint32_t a, uint32_t c) {
    asm volatile("mbarrier.init.shared.b64 [%0], %1;" :: "r"(a), "r"(c) : "memory");
}
__device__ __forceinline__ void mbar_expect_tx(uint32_t a, uint32_t bytes) {
    asm volatile("mbarrier.arrive.expect_tx.shared.b64 _, [%0], %1;"
                 :: "r"(a), "r"(bytes) : "memory");
}
__device__ __forceinline__ void mbar_wait(uint32_t a, uint32_t parity) {
    asm volatile(
        "{\n\t"
        ".reg .pred P1;\n\t"
        "LWAIT_%=:\n\t"
        "mbarrier.try_wait.parity.acquire.cta.shared::cta.b64 P1, [%0], %1, 0x989680;\n\t"
        "@!P1 bra LWAIT_%=;\n\t"
        "}"
        :: "r"(a), "r"(parity) : "memory");
}
__device__ __forceinline__ void fence_pa() {
    asm volatile("fence.proxy.async.shared::cta;" ::: "memory");
}
__device__ __forceinline__ void tma2d(uint32_t dst, const void* map,
                                      int cx, int cy, uint32_t mbar) {
    asm volatile(
        "cp.async.bulk.tensor.2d.shared::cta.global.tile.mbarrier::complete_tx::bytes "
        "[%0], [%1, {%2, %3}], [%4];"
        :: "r"(dst), "l"(map), "r"(cx), "r"(cy), "r"(mbar) : "memory");
}
__device__ __forceinline__ void ldmatrix_x4(uint32_t* r, uint32_t addr) {
    asm volatile("ldmatrix.sync.aligned.m8n8.x4.shared.b16 {%0,%1,%2,%3}, [%4];"
                 : "=r"(r[0]), "=r"(r[1]), "=r"(r[2]), "=r"(r[3]) : "r"(addr));
}
__device__ __forceinline__ void mma16816(float* d, const uint32_t* a,
                                         uint32_t b0, uint32_t b1) {
    asm volatile(
        "mma.sync.aligned.m16n8k16.row.col.f32.f16.f16.f32 "
        "{%0,%1,%2,%3}, {%4,%5,%6,%7}, {%8,%9}, {%0,%1,%2,%3};"
        : "+f"(d[0]), "+f"(d[1]), "+f"(d[2]), "+f"(d[3])
        : "r"(a[0]), "r"(a[1]), "r"(a[2]), "r"(a[3]), "r"(b0), "r"(b1));
}

// TMA SW128 swizzle on 128-byte rows: chunk' = chunk ^ (row & 7)
// (byte_off ^ ((byte_off>>3)&0x70) specialised to row*128 + chunk*16)
__device__ __forceinline__ uint32_t sw_off(int row, int kchunk) {
    return (uint32_t)(row * 128 + ((kchunk ^ (row & 7)) * 16));
}

// ---------------------------------------------------------------------------
// Convert kernels: fp32 -> fp16 operand scratch (8 elems/thread, 16B stores)
// ---------------------------------------------------------------------------
__global__ void __launch_bounds__(256)
convert_A_kernel(const float* __restrict__ x_t, const float* __restrict__ h_prev) {
    int i = blockIdx.x * 256 + threadIdx.x;   // one 8-element chunk
    int row  = i >> 9;                        // CDIM/8 = 512 chunks per row
    int col8 = (i & 511) * 8;
    const float* src = (col8 < HID) ? (h_prev + (size_t)row * HID + col8)
                                    : (x_t + (size_t)row * 2048 + (col8 - HID));
    float4 v0 = *(const float4*)(src);
    float4 v1 = *(const float4*)(src + 4);
    __half2 h[4] = { __floats2half2_rn(v0.x, v0.y), __floats2half2_rn(v0.z, v0.w),
                     __floats2half2_rn(v1.x, v1.y), __floats2half2_rn(v1.z, v1.w) };
    *(uint4*)(g_A + (size_t)row * CDIM + col8) = *(const uint4*)h;
}

__global__ void __launch_bounds__(256)
convert_W_kernel(const float* __restrict__ Wf, const float* __restrict__ Wi,
                 const float* __restrict__ Wc, const float* __restrict__ Wo) {
    int i = blockIdx.x * 256 + threadIdx.x;
    int row  = i >> 9;                        // 0..8191 (interleaved row 4j+g)
    int col8 = (i & 511) * 8;
    int g = row & 3;
    int j = row >> 2;
    const float* srcm = (g == 0) ? Wf : (g == 1) ? Wi : (g == 2) ? Wc : Wo;
    const float* src = srcm + (size_t)j * CDIM + col8;
    float4 v0 = *(const float4*)(src);
    float4 v1 = *(const float4*)(src + 4);
    __half2 h[4] = { __floats2half2_rn(v0.x, v0.y), __floats2half2_rn(v0.z, v0.w),
                     __floats2half2_rn(v1.x, v1.y), __floats2half2_rn(v1.z, v1.w) };
    *(uint4*)(g_W + (size_t)row * CDIM + col8) = *(const uint4*)h;
}

// ---------------------------------------------------------------------------
// Fused GEMM (mma.sync) + LSTM epilogue. TMA producer, 4-stage mbar pipeline.
// 512 threads = 16 warps in a 4x4 grid; warp tile 32(m) x 64(n)
// ---------------------------------------------------------------------------
__global__ void __launch_bounds__(512, 1)
lstm_gemm_kernel(const __grid_constant__ CUtensorMap tmA,
                 const __grid_constant__ CUtensorMap tmB,
                 const float* __restrict__ c_prev,
                 const float* __restrict__ bf_, const float* __restrict__ bi_,
                 const float* __restrict__ bc_, const float* __restrict__ bo_,
                 float* __restrict__ out) {
    extern __shared__ char smem_raw[];
    const uint32_t sb0 = smem_u32(smem_raw);
    const uint32_t sb  = (sb0 + 1023u) & ~1023u;   // 1024-aligned base
    char* smema = smem_raw + (sb - sb0);

    const int tid  = threadIdx.x;
    const int lane = tid & 31;
    const int wid  = tid >> 5;
    const int wm   = wid & 3;   // warp row (m tile = wm*32)
    const int wn   = wid >> 2;  // warp col (n tile = wn*64)
    const int m0 = blockIdx.x * BM;
    const int n0 = blockIdx.y * BN;

    // mbarrier init + prologue TMA loads (stages 0..2)
    if (tid == 0) {
        #pragma unroll
        for (int s = 0; s < STAGES; s++) mbar_init(sb + 8 * s, 1);
        fence_pa();
    }
    __syncthreads();
    if (tid == 0) {
        #pragma unroll
        for (int s = 0; s < STAGES - 1; s++) {
            uint32_t mb = sb + 8 * s;
            uint32_t dA = sb + OFF_STG + s * STG_BYTES;
            mbar_expect_tx(mb, STG_BYTES);
            tma2d(dA, &tmA, s * BK, m0, mb);
            tma2d(dA + A_BYTES, &tmB, s * BK, n0, mb);
        }
    }

    float acc[2][8][4];
    #pragma unroll
    for (int mi = 0; mi < 2; mi++)
        #pragma unroll
        for (int ni = 0; ni < 8; ni++)
            #pragma unroll
            for (int q = 0; q < 4; q++) acc[mi][ni][q] = 0.0f;

    // ldmatrix lane address components (same fragment mapping as R8 -- verified)
    const int a_row_l = lane & 15;                        // A rows
    const int a_ksel  = lane >> 4;                        // A k-octet select
    const int b_row_l = (lane & 7) + ((lane & 16) >> 1);  // B: two n-octets
    const int b_ksel  = (lane >> 3) & 1;

    for (int k = 0; k < NKITERS; k++) {
        mbar_wait(sb + 8 * (k & 3), (k >> 2) & 1);   // stage k resident
        __syncthreads();                             // all warps done with k-1
        if (tid == 0 && k + 3 < NKITERS) {           // refill freed slot
            int s = (k + 3) & 3;
            uint32_t mb = sb + 8 * s;
            uint32_t dA = sb + OFF_STG + s * STG_BYTES;
            mbar_expect_tx(mb, STG_BYTES);
            tma2d(dA, &tmA, (k + 3) * BK, m0, mb);
            tma2d(dA + A_BYTES, &tmB, (k + 3) * BK, n0, mb);
        }

        const uint32_t sA = sb + OFF_STG + (k & 3) * STG_BYTES;
        const uint32_t sB = sA + A_BYTES;

        #pragma unroll
        for (int ks = 0; ks < 4; ks++) {      // four K=16 steps per BK=64
            uint32_t a[2][4];
            #pragma unroll
            for (int mi = 0; mi < 2; mi++) {
                int row = wm * 32 + mi * 16 + a_row_l;
                int kc  = ks * 2 + a_ksel;
                ldmatrix_x4(a[mi], sA + sw_off(row, kc));
            }
            #pragma unroll
            for (int np = 0; np < 4; np++) {  // each x4 yields 2 n-octets
                int nrow = wn * 64 + np * 16 + b_row_l;
                int kc   = ks * 2 + b_ksel;
                uint32_t b[4];
                ldmatrix_x4(b, sB + sw_off(nrow, kc));
                #pragma unroll
                for (int mi = 0; mi < 2; mi++) {
                    mma16816(acc[mi][np * 2 + 0], a[mi], b[0], b[1]);
                    mma16816(acc[mi][np * 2 + 1], a[mi], b[2], b[3]);
                }
            }
        }
    }
    __syncthreads();

    // --- Fused epilogue: two 128-col passes through padded SMEM ---
    float* smG  = (float*)(smema + OFF_STG);
    float* outH = out;
    float* outC = out + (size_t)BATCH * HID;

    #pragma unroll
    for (int p = 0; p < 2; p++) {
        if ((wn >> 1) == p) {            // warps owning cols [p*128, p*128+128)
            int colbase = (wn & 1) * 64;
            #pragma unroll
            for (int mi = 0; mi < 2; mi++)
                #pragma unroll
                for (int ni = 0; ni < 8; ni++) {
                    int r  = wm * 32 + mi * 16 + (lane >> 2);
                    int cc = colbase + ni * 8 + (lane & 3) * 2;
                    *(float2*)&smG[r * SMG_STRIDE + cc] =
                        make_float2(acc[mi][ni][0], acc[mi][ni][1]);
                    *(float2*)&smG[(r + 8) * SMG_STRIDE + cc] =
                        make_float2(acc[mi][ni][2], acc[mi][ni][3]);
                }
        }
        __syncthreads();

        const int j0 = (n0 >> 2) + p * 32;
        #pragma unroll
        for (int it = 0; it < 8; it++) {     // 4096 outputs / 512 threads
            int idx = tid + it * 512;
            int r = idx >> 5, jl = idx & 31;
            float4 g4 = *(const float4*)&smG[r * SMG_STRIDE + jl * 4];
            int j = j0 + jl;
            float gf = g4.x + __ldg(bf_ + j);
            float gi = g4.y + __ldg(bi_ + j);
            float gc = g4.z + __ldg(bc_ + j);
            float go = g4.w + __ldg(bo_ + j);
            float f  = 1.0f / (1.0f + __expf(-gf));
            float ii = 1.0f / (1.0f + __expf(-gi));
            float ct = tanhf(gc);
            float o  = 1.0f / (1.0f + __expf(-go));
            size_t gidx = (size_t)(m0 + r) * HID + j;
            float cn = f * c_prev[gidx] + ii * ct;
            outC[gidx] = cn;
            outH[gidx] = o * tanhf(cn);
        }
        __syncthreads();   // buffer reuse between passes
    }
}

// ---------------------------------------------------------------------------
// Host: tensor-map construction (driver entry point, no -lcuda link) + launch
// ---------------------------------------------------------------------------
typedef CUresult (*EncodeTiledFn)(
    CUtensorMap*, CUtensorMapDataType, cuuint32_t, void*,
    const cuuint64_t*, const cuuint64_t*, const cuuint32_t*, const cuuint32_t*,
    CUtensorMapInterleave, CUtensorMapSwizzle, CUtensorMapL2promotion,
    CUtensorMapFloatOOBfill);

static void build_map(EncodeTiledFn enc, CUtensorMap* m, void* base,
                      uint64_t rows, uint32_t box_rows) {
    cuuint64_t dims[2]    = { CDIM, rows };
    cuuint64_t strides[1] = { CDIM * 2 };       // bytes, dim1 stride
    cuuint32_t box[2]     = { BK, box_rows };   // 64 halves = 128 B = SW128 span
    cuuint32_t estr[2]    = { 1, 1 };
    enc(m, CU_TENSOR_MAP_DATA_TYPE_FLOAT16, 2, base, dims, strides, box, estr,
        CU_TENSOR_MAP_INTERLEAVE_NONE, CU_TENSOR_MAP_SWIZZLE_128B,
        CU_TENSOR_MAP_L2_PROMOTION_L2_128B, CU_TENSOR_MAP_FLOAT_OOB_FILL_NONE);
}

extern "C" void kernel_launch(void* const* d_in, const int* in_sizes, int n_in,
                              void* d_out, int out_size) {
    const float* x_t    = (const float*)d_in[0];
    const float* h_prev = (const float*)d_in[1];
    const float* c_prev = (const float*)d_in[2];
    const float* W_f = (const float*)d_in[3];
    const float* b_f = (const float*)d_in[4];
    const float* W_i = (const float*)d_in[5];
    const float* b_i = (const float*)d_in[6];
    const float* W_c = (const float*)d_in[7];
    const float* b_c = (const float*)d_in[8];
    const float* W_o = (const float*)d_in[9];
    const float* b_o = (const float*)d_in[10];
    float* out = (float*)d_out;

    // Fetch cuTensorMapEncodeTiled through the runtime (header types only; no -lcuda)
    void* fn = nullptr;
    cudaDriverEntryPointQueryResult qr;
#if CUDART_VERSION >= 12050
    cudaGetDriverEntryPointByVersion("cuTensorMapEncodeTiled", &fn, 12000,
                                     cudaEnableDefault, &qr);
#else
    cudaGetDriverEntryPoint("cuTensorMapEncodeTiled", &fn, cudaEnableDefault, &qr);
#endif
    EncodeTiledFn enc = (EncodeTiledFn)fn;

    void *pA = nullptr, *pW = nullptr;
    cudaGetSymbolAddress(&pA, g_A);
    cudaGetSymbolAddress(&pW, g_W);

    CUtensorMap tmA, tmB;
    build_map(enc, &tmA, pA, BATCH, BM);   // A: box 64 x 128
    build_map(enc, &tmB, pW, NDIM, BN);    // B: box 64 x 256

    cudaFuncSetAttribute(lstm_gemm_kernel,
                         cudaFuncAttributeMaxDynamicSharedMemorySize, SMEM_TOTAL);

    convert_A_kernel<<<(BATCH * (CDIM / 8)) / 256, 256>>>(x_t, h_prev);
    convert_W_kernel<<<(NDIM * (CDIM / 8)) / 256, 256>>>(W_f, W_i, W_c, W_o);

    dim3 grid(BATCH / BM, NDIM / BN);   // 32 x 32 = 1024 CTAs
    lstm_gemm_kernel<<<grid, 512, SMEM_TOTAL>>>(tmA, tmB, c_prev,
                                                b_f, b_i, b_c, b_o, out);
}